// round 13
// baseline (speedup 1.0000x reference)
#include <cuda_runtime.h>
#include <cuda_bf16.h>
#include <cuda_fp16.h>
#include <cstdint>

#define LMAX 10
#define NI   121
#define DTOT 1771
#define PSI_SCALE 0.005524271728019903f   // 1/(sqrt(512)*sqrt(64))

// scratch
__device__ __half g_xt[512 * 64 * NI];     // [l-block][(b*d+m)][e]  fp16
__device__ __half g_psi[NI * 4096];        // [i][g*64+e]            fp16
__device__ float  g_psif[8 * NI * 4096];   // k-split partials

// conv grid: per l, 4d mtiles x ng u-groups (ng = ceil(d/4))
__constant__ int c_lstart[12] = {0,4,16,56,112,220,352,560,800,1140,1520,2024};
__constant__ int c_ng[11]     = {1,1,2,2,3,3,4,4,5,5,6};
__constant__ int c_off[11]    = {0,1,10,35,84,165,286,455,680,969,1330};

// ---------------------------------------------------------------------------
__device__ __forceinline__ uint32_t su32(const void* p) {
    return (uint32_t)__cvta_generic_to_shared(p);
}
__device__ __forceinline__ void ldsm4(uint32_t* r, uint32_t addr) {
    asm volatile("ldmatrix.sync.aligned.m8n8.x4.shared.b16 {%0,%1,%2,%3}, [%4];"
                 : "=r"(r[0]), "=r"(r[1]), "=r"(r[2]), "=r"(r[3]) : "r"(addr));
}
__device__ __forceinline__ void mma_bf16(float* c, const uint32_t* a,
                                         uint32_t b0, uint32_t b1) {
    asm volatile(
        "mma.sync.aligned.m16n8k16.row.col.f32.bf16.bf16.f32 "
        "{%0,%1,%2,%3}, {%4,%5,%6,%7}, {%8,%9}, {%0,%1,%2,%3};"
        : "+f"(c[0]), "+f"(c[1]), "+f"(c[2]), "+f"(c[3])
        : "r"(a[0]), "r"(a[1]), "r"(a[2]), "r"(a[3]), "r"(b0), "r"(b1));
}
__device__ __forceinline__ void mma_f16(float* c, const uint32_t* a,
                                        uint32_t b0, uint32_t b1) {
    asm volatile(
        "mma.sync.aligned.m16n8k16.row.col.f32.f16.f16.f32 "
        "{%0,%1,%2,%3}, {%4,%5,%6,%7}, {%8,%9}, {%0,%1,%2,%3};"
        : "+f"(c[0]), "+f"(c[1]), "+f"(c[2]), "+f"(c[3])
        : "r"(a[0]), "r"(a[1]), "r"(a[2]), "r"(a[3]), "r"(b0), "r"(b1));
}
__device__ __forceinline__ void cp16(uint32_t dst, const void* src) {
    asm volatile("cp.async.cg.shared.global [%0], [%1], 16;" :: "r"(dst), "l"(src));
}
#define CCOMMIT() asm volatile("cp.async.commit_group;")
#define CWAIT(n)  asm volatile("cp.async.wait_group %0;" :: "n"(n))

// shared tile geometry (row = 64 vals * 2B = 128B data, padded to 144B)
#define AST      144
#define OFF_AL   18432     // pre kernel
#define OFF_BH   36864
#define OFF_BL   46080
#define DSMEM_PRE 55296

#define OFF_B0   18432     // conv kernel
#define OFF_B1   27648
#define OFF_EPI  36864
#define DSMEM_CONV 70144   // 36864 + 128*65*4

#define MMA_TERM(A, B)                                                   \
    do {                                                                 \
        _Pragma("unroll")                                                \
        for (int mt = 0; mt < 2; mt++) {                                 \
            _Pragma("unroll")                                            \
            for (int h = 0; h < 2; h++) {                                \
                mma_bf16(acc[mt][2 * h + 0], A[mt], B[h][0], B[h][2]);   \
                mma_bf16(acc[mt][2 * h + 1], A[mt], B[h][1], B[h][3]);   \
            }                                                            \
        }                                                                \
    } while (0)

// ---------------------------------------------------------------------------
// Fused pre-kernel: blocks [0,512) = psi k-split GEMM (3-term bf16 split),
// blocks [512,1024) = x transpose.  (unchanged from R12)
// ---------------------------------------------------------------------------
__global__ __launch_bounds__(256) void fused_pre_kernel(const float* __restrict__ Y,
                                                        const float* __restrict__ W,
                                                        const float* __restrict__ x) {
    extern __shared__ __align__(16) char sb[];
    const int tid = threadIdx.x;

    if (blockIdx.x >= 512) {
        float* s = (float*)sb;
        const int b = blockIdx.x - 512;
        const float* xb = x + b * (64 * NI);
        for (int k = tid; k < 64 * NI; k += 256) s[k] = xb[k];
        __syncthreads();
        for (int k = tid; k < 64 * NI; k += 256) {
            int i = k >> 6, e = k & 63;
            float v = s[e * NI + i];
            int l = (int)sqrtf((float)i + 0.5f);
            int d = 2 * l + 1, m = i - l * l;
            g_xt[32768 * l * l + (b * d + m) * 64 + e] = __float2half_rn(v);
        }
        return;
    }

    const int wid  = tid >> 5;
    const int lane = tid & 31;
    const int g    = blockIdx.x & 63;
    const int ks   = blockIdx.x >> 6;
    const int kk   = ks * 64;

    const int wm = wid & 3;
    const int wn = wid >> 2;
    const uint32_t rowA = (wm * 32 + (lane & 15)) * AST + (lane >> 4) * 16;
    const uint32_t rowB = (wn * 32 + (lane & 15)) * AST + (lane >> 4) * 16;
    const uint32_t aHi = su32(sb) + rowA;
    const uint32_t aLo = su32(sb) + OFF_AL + rowA;
    const uint32_t bHi = su32(sb) + OFF_BH + rowB;
    const uint32_t bLo = su32(sb) + OFF_BL + rowB;

    float acc[2][4][4];
    #pragma unroll
    for (int mt = 0; mt < 2; mt++)
        #pragma unroll
        for (int nt = 0; nt < 4; nt++)
            #pragma unroll
            for (int q = 0; q < 4; q++) acc[mt][nt][q] = 0.f;

    #pragma unroll
    for (int it = 0; it < 16; it++) {
        int idx = it * 256 + tid;
        int kp = idx >> 7;
        int i  = idx & 127;
        float v0 = 0.f, v1 = 0.f;
        if (i < NI) {
            v0 = Y[(kk + 2 * kp) * NI + i];
            v1 = Y[(kk + 2 * kp + 1) * NI + i];
        }
        __nv_bfloat16 h0 = __float2bfloat16(v0);
        __nv_bfloat16 h1 = __float2bfloat16(v1);
        __nv_bfloat16 l0 = __float2bfloat16(v0 - __bfloat162float(h0));
        __nv_bfloat16 l1 = __float2bfloat16(v1 - __bfloat162float(h1));
        *(uint32_t*)(sb + i * AST + kp * 4) =
            (uint32_t)__bfloat16_as_ushort(h0) | ((uint32_t)__bfloat16_as_ushort(h1) << 16);
        *(uint32_t*)(sb + OFF_AL + i * AST + kp * 4) =
            (uint32_t)__bfloat16_as_ushort(l0) | ((uint32_t)__bfloat16_as_ushort(l1) << 16);
    }
    #pragma unroll
    for (int it = 0; it < 4; it++) {
        int idx = it * 256 + tid;
        int e = idx >> 4, j = idx & 15;
        float4 v = *(const float4*)&W[(size_t)(e * 64 + g) * 512 + kk + j * 4];
        __nv_bfloat16 h0 = __float2bfloat16(v.x), h1 = __float2bfloat16(v.y);
        __nv_bfloat16 h2 = __float2bfloat16(v.z), h3 = __float2bfloat16(v.w);
        __nv_bfloat16 l0 = __float2bfloat16(v.x - __bfloat162float(h0));
        __nv_bfloat16 l1 = __float2bfloat16(v.y - __bfloat162float(h1));
        __nv_bfloat16 l2 = __float2bfloat16(v.z - __bfloat162float(h2));
        __nv_bfloat16 l3 = __float2bfloat16(v.w - __bfloat162float(h3));
        uint2 hi, lo;
        hi.x = (uint32_t)__bfloat16_as_ushort(h0) | ((uint32_t)__bfloat16_as_ushort(h1) << 16);
        hi.y = (uint32_t)__bfloat16_as_ushort(h2) | ((uint32_t)__bfloat16_as_ushort(h3) << 16);
        lo.x = (uint32_t)__bfloat16_as_ushort(l0) | ((uint32_t)__bfloat16_as_ushort(l1) << 16);
        lo.y = (uint32_t)__bfloat16_as_ushort(l2) | ((uint32_t)__bfloat16_as_ushort(l3) << 16);
        *(uint2*)(sb + OFF_BH + e * AST + j * 8) = hi;
        *(uint2*)(sb + OFF_BL + e * AST + j * 8) = lo;
    }
    __syncthreads();

    #pragma unroll
    for (int kss = 0; kss < 4; kss++) {
        const uint32_t kb = kss * 32;
        uint32_t ah[2][4], al[2][4], bh[2][4], bl[2][4];
        ldsm4(ah[0], aHi + kb);
        ldsm4(ah[1], aHi + 16 * AST + kb);
        ldsm4(al[0], aLo + kb);
        ldsm4(al[1], aLo + 16 * AST + kb);
        ldsm4(bh[0], bHi + kb);
        ldsm4(bh[1], bHi + 16 * AST + kb);
        ldsm4(bl[0], bLo + kb);
        ldsm4(bl[1], bLo + 16 * AST + kb);
        MMA_TERM(ah, bh);
        MMA_TERM(ah, bl);
        MMA_TERM(al, bh);
    }

    float* dst = g_psif + (size_t)ks * (NI * 4096);
    const int gID = lane >> 2;
    const int tig = lane & 3;
    #pragma unroll
    for (int mt = 0; mt < 2; mt++) {
        #pragma unroll
        for (int nt = 0; nt < 4; nt++) {
            int row = wm * 32 + mt * 16 + gID;
            int col = g * 64 + wn * 32 + nt * 8 + tig * 2;
            if (row < NI)
                *(float2*)&dst[row * 4096 + col] =
                    make_float2(acc[mt][nt][0], acc[mt][nt][1]);
            if (row + 8 < NI)
                *(float2*)&dst[(row + 8) * 4096 + col] =
                    make_float2(acc[mt][nt][2], acc[mt][nt][3]);
        }
    }
}

// ---------------------------------------------------------------------------
__global__ __launch_bounds__(256) void pack_kernel() {
    const int idx = blockIdx.x * 256 + threadIdx.x;
    const int N = NI * 4096;
    float v = 0.f;
    #pragma unroll
    for (int ks = 0; ks < 8; ks++) v += g_psif[idx + ks * N];
    g_psi[idx] = __float2half_rn(v * PSI_SCALE);
}

// ---------------------------------------------------------------------------
// Conv: CTA = (l, mtile, u-group of up to 4). A fragments cached in registers
// across the u loop; B double-buffered via cp.async.
// ---------------------------------------------------------------------------
__global__ __launch_bounds__(256, 2) void conv_kernel(float* __restrict__ out) {
    extern __shared__ __align__(16) char sb[];

    const int tid  = threadIdx.x;
    const int wid  = tid >> 5;
    const int lane = tid & 31;
    const int bid  = blockIdx.x;

    int l = 0;
    #pragma unroll
    for (int t = 1; t <= LMAX; t++)
        if (bid >= c_lstart[t]) l = t;
    const int d     = 2 * l + 1;
    const int l2    = l * l;
    const int ng    = c_ng[l];
    const int rel   = bid - c_lstart[l];
    const int mtile = rel / ng;
    const int ug    = rel - mtile * ng;
    const int r0    = mtile * 128;
    const int u0    = ug * 4;
    const int ucnt  = min(4, d - u0);

    const uint32_t sbase = su32(sb);

    // ---- prologue: async-load A tile + B(u0) [group 0], B(u0+1) [group 1]
    {
        const __half* Abase = g_xt + (size_t)l2 * 32768 + (size_t)r0 * 64;
        #pragma unroll
        for (int it = 0; it < 4; it++) {
            int idx = it * 256 + tid;
            int r = idx >> 3, j = idx & 7;
            cp16(sbase + r * AST + j * 16, Abase + idx * 8);
        }
        const __half* B0 = g_psi + (size_t)(l2 + u0) * 4096;
        #pragma unroll
        for (int it = 0; it < 2; it++) {
            int idx = it * 256 + tid;
            int n = idx >> 3, j = idx & 7;
            cp16(sbase + OFF_B0 + n * AST + j * 16, B0 + idx * 8);
        }
        CCOMMIT();
        if (ucnt > 1) {
            const __half* B1 = g_psi + (size_t)(l2 + u0 + 1) * 4096;
            #pragma unroll
            for (int it = 0; it < 2; it++) {
                int idx = it * 256 + tid;
                int n = idx >> 3, j = idx & 7;
                cp16(sbase + OFF_B1 + n * AST + j * 16, B1 + idx * 8);
            }
            CCOMMIT();
        }
    }

    const int wm = wid & 3;
    const int wn = wid >> 2;
    const uint32_t aBase = sbase + (wm * 32 + (lane & 15)) * AST + (lane >> 4) * 16;
    const uint32_t rowB  = (wn * 32 + (lane & 15)) * AST + (lane >> 4) * 16;

    uint32_t a[4][2][4];            // A fragments cached across u loop
    float* sC = (float*)(sb + OFF_EPI);
    const int gID = lane >> 2;
    const int tig = lane & 3;
    const int offl = c_off[l];

    for (int ui = 0; ui < ucnt; ui++) {
        if (ui + 1 < ucnt) { CWAIT(1); } else { CWAIT(0); }
        __syncthreads();

        if (ui == 0) {
            #pragma unroll
            for (int ks = 0; ks < 4; ks++) {
                ldsm4(a[ks][0], aBase + ks * 32);
                ldsm4(a[ks][1], aBase + 16 * AST + ks * 32);
            }
        }

        const uint32_t bBase = sbase + ((ui & 1) ? OFF_B1 : OFF_B0) + rowB;

        float acc[2][4][4];
        #pragma unroll
        for (int mt = 0; mt < 2; mt++)
            #pragma unroll
            for (int nt = 0; nt < 4; nt++)
                #pragma unroll
                for (int q = 0; q < 4; q++) acc[mt][nt][q] = 0.f;

        #pragma unroll
        for (int ks = 0; ks < 4; ks++) {
            uint32_t b[2][4];
            ldsm4(b[0], bBase + ks * 32);
            ldsm4(b[1], bBase + 16 * AST + ks * 32);
            #pragma unroll
            for (int mt = 0; mt < 2; mt++) {
                #pragma unroll
                for (int h = 0; h < 2; h++) {
                    mma_f16(acc[mt][2 * h + 0], a[ks][mt], b[h][0], b[h][2]);
                    mma_f16(acc[mt][2 * h + 1], a[ks][mt], b[h][1], b[h][3]);
                }
            }
        }

        // sync: previous epilogue reads done + all ldsm of this B done
        __syncthreads();

        // stage fp32 tile, stride 65
        #pragma unroll
        for (int mt = 0; mt < 2; mt++) {
            #pragma unroll
            for (int nt = 0; nt < 4; nt++) {
                int row = wm * 32 + mt * 16 + gID;
                int col = wn * 32 + nt * 8 + tig * 2;
                sC[row * 65 + col]           = acc[mt][nt][0];
                sC[row * 65 + col + 1]       = acc[mt][nt][1];
                sC[(row + 8) * 65 + col]     = acc[mt][nt][2];
                sC[(row + 8) * 65 + col + 1] = acc[mt][nt][3];
            }
        }

        // prefetch B(ui+2) into the buffer just consumed
        if (ui + 2 < ucnt) {
            const __half* Bn = g_psi + (size_t)(l2 + u0 + ui + 2) * 4096;
            const uint32_t dstb = sbase + ((ui & 1) ? OFF_B1 : OFF_B0);
            #pragma unroll
            for (int it = 0; it < 2; it++) {
                int idx = it * 256 + tid;
                int n = idx >> 3, j = idx & 7;
                cp16(dstb + n * AST + j * 16, Bn + idx * 8);
            }
            CCOMMIT();
        }
        __syncthreads();

        // scatter stores
        const int u = u0 + ui;
        #pragma unroll
        for (int it = 0; it < 32; it++) {
            int linear = it * 256 + tid;
            int g = linear >> 7;
            int r = linear & 127;
            int R = r0 + r;
            int b = R / d;
            int m = R - b * d;
            out[(size_t)b * (64 * DTOT) + (size_t)g * DTOT + offl + u * d + m]
                = sC[r * 65 + g];
        }
    }
}

// ---------------------------------------------------------------------------
extern "C" void kernel_launch(void* const* d_in, const int* in_sizes, int n_in,
                              void* d_out, int out_size) {
    const float *x = nullptr, *w = nullptr, *Y = nullptr;
    for (int i = 0; i < n_in; i++) {
        if (in_sizes[i] == 512 * 64 * NI)       x = (const float*)d_in[i];
        else if (in_sizes[i] == 64 * 64 * 512)  w = (const float*)d_in[i];
        else if (in_sizes[i] == 512 * NI)       Y = (const float*)d_in[i];
    }
    float* out = (float*)d_out;

    cudaFuncSetAttribute(fused_pre_kernel, cudaFuncAttributeMaxDynamicSharedMemorySize, DSMEM_PRE);
    cudaFuncSetAttribute(conv_kernel,      cudaFuncAttributeMaxDynamicSharedMemorySize, DSMEM_CONV);

    fused_pre_kernel<<<1024, 256, DSMEM_PRE>>>(Y, w, x);
    pack_kernel<<<NI * 4096 / 256, 256>>>();
    conv_kernel<<<2024, 256, DSMEM_CONV>>>(out);
}